// round 1
// baseline (speedup 1.0000x reference)
#include <cuda_runtime.h>
#include <math.h>

// ---------------- problem constants ----------------
#define BATCH 2
#define SEQ   2048
#define DM    5120
#define NH    8
#define DH    640
#define DR    16
#define SPLITD 624
#define DKV   128
#define MROWS (BATCH*SEQ)   // 4096

// ---------------- scratch (device globals; no allocs allowed) ----------------
__device__ float g_ckv [MROWS*DKV];
__device__ float g_cq  [MROWS*DKV];
__device__ float g_qrot[MROWS*DKV];
__device__ float g_krot[MROWS*DKV];
__device__ float g_q   [(size_t)MROWS*DM];
__device__ float g_k   [(size_t)MROWS*DM];
__device__ float g_v   [(size_t)MROWS*DM];
__device__ float g_ao  [(size_t)MROWS*DM];
__device__ float g_sc  [(size_t)BATCH*NH*SEQ*SEQ];   // 256 MB attention scores

// ---------------- generic batched SGEMM ----------------
#define BM 128
#define BN 128
#define BK 16
#define TM 8
#define TN 8

template<bool TB>
__global__ __launch_bounds__(256)
void sgemm_k(const float* __restrict__ A, const float* __restrict__ B,
             float* __restrict__ C, const float* __restrict__ bias,
             int M, int N, int K, int lda, int ldb, int ldc, float alpha,
             long long sAhi, long long sAlo, long long sBhi, long long sBlo,
             long long sChi, long long sClo, long long sBiasLo, int zdiv)
{
    int z  = blockIdx.z;
    int zh = z / zdiv, zl = z % zdiv;
    A += zh * sAhi + zl * sAlo;
    B += zh * sBhi + zl * sBlo;
    C += zh * sChi + zl * sClo;
    if (bias) bias += zl * sBiasLo;

    __shared__ float As[BK][BM + 4];
    __shared__ float Bs[BK][BN + 4];

    int tid = threadIdx.x;
    int tx = tid & 15, ty = tid >> 4;
    int row0 = blockIdx.y * BM, col0 = blockIdx.x * BN;

    float acc[TM][TN];
#pragma unroll
    for (int i = 0; i < TM; i++)
#pragma unroll
        for (int j = 0; j < TN; j++) acc[i][j] = 0.0f;

    for (int k0 = 0; k0 < K; k0 += BK) {
        // ---- load A tile (coalesced along K, 16-wide) ----
#pragma unroll
        for (int i = 0; i < 8; i++) {
            int idx = tid + i * 256;
            int m = idx >> 4, kk = idx & 15;
            int gr = row0 + m, gc = k0 + kk;
            float v = 0.0f;
            if (gr < M && gc < K) v = A[(size_t)gr * lda + gc];
            As[kk][m] = v;
        }
        // ---- load B tile ----
#pragma unroll
        for (int i = 0; i < 8; i++) {
            int idx = tid + i * 256;
            if (TB) {
                int n = idx >> 4, kk = idx & 15;
                int gn = col0 + n, gk = k0 + kk;
                float v = 0.0f;
                if (gn < N && gk < K) v = B[(size_t)gn * ldb + gk];
                Bs[kk][n] = v;
            } else {
                int kk = idx >> 7, n = idx & 127;
                int gn = col0 + n, gk = k0 + kk;
                float v = 0.0f;
                if (gn < N && gk < K) v = B[(size_t)gk * ldb + gn];
                Bs[kk][n] = v;
            }
        }
        __syncthreads();
#pragma unroll
        for (int kk = 0; kk < BK; kk++) {
            float a[TM], b[TN];
#pragma unroll
            for (int i = 0; i < TM; i++) a[i] = As[kk][ty * TM + i];
#pragma unroll
            for (int j = 0; j < TN; j++) b[j] = Bs[kk][tx * TN + j];
#pragma unroll
            for (int i = 0; i < TM; i++)
#pragma unroll
                for (int j = 0; j < TN; j++) acc[i][j] += a[i] * b[j];
        }
        __syncthreads();
    }

#pragma unroll
    for (int i = 0; i < TM; i++) {
        int r = row0 + ty * TM + i;
        if (r >= M) continue;
#pragma unroll
        for (int j = 0; j < TN; j++) {
            int c = col0 + tx * TN + j;
            if (c < N) {
                float o = alpha * acc[i][j];
                if (bias) o += bias[c];
                C[(size_t)r * ldc + c] = o;
            }
        }
    }
}

// ---------------- RoPE ----------------
// rot: [MROWS, NH*16] linear. Writes rotated values into dst (q or k buffer,
// layout [MROWS, DM]) at head*640+624+d. If rout != nullptr also writes the
// flat [MROWS, 128] rotated tensor (k_rot output).
__global__ void rope_k(const float* __restrict__ rot, float* __restrict__ dst,
                       float* __restrict__ rout)
{
    int idx = blockIdx.x * blockDim.x + threadIdx.x;
    if (idx >= MROWS * DKV) return;
    int m = idx >> 7;
    int c = idx & 127;
    int h = c >> 4;
    int d = c & 15;
    int j = d & 7;
    int s = m & (SEQ - 1);
    float t = (float)s * (1.0f / 40.0f);
    float invf = __expf(-(float)j * 0.86346941f);  // ln(1000)/8
    float ang = t * invf;
    float sn, cs;
    sincosf(ang, &sn, &cs);
    float x = rot[idx];
    float p = rot[(m << 7) + (h << 4) + ((d < 8) ? d + 8 : d - 8)];
    float val = x * cs + ((d < 8) ? -p : p) * sn;
    dst[(size_t)m * DM + h * DH + SPLITD + d] = val;
    if (rout) rout[idx] = val;
}

// ---------------- softmax over rows of length SEQ ----------------
__global__ __launch_bounds__(256) void softmax_k(float* __restrict__ s)
{
    float* row = s + (size_t)blockIdx.x * SEQ;
    int t = threadIdx.x;
    float v[8];
    float mx = -1e30f;
#pragma unroll
    for (int i = 0; i < 8; i++) { v[i] = row[t + i * 256]; mx = fmaxf(mx, v[i]); }
    __shared__ float red[256];
    red[t] = mx; __syncthreads();
    for (int off = 128; off > 0; off >>= 1) {
        if (t < off) red[t] = fmaxf(red[t], red[t + off]);
        __syncthreads();
    }
    mx = red[0]; __syncthreads();
    float sum = 0.0f;
#pragma unroll
    for (int i = 0; i < 8; i++) { v[i] = __expf(v[i] - mx); sum += v[i]; }
    red[t] = sum; __syncthreads();
    for (int off = 128; off > 0; off >>= 1) {
        if (t < off) red[t] += red[t + off];
        __syncthreads();
    }
    float inv = 1.0f / red[0];
#pragma unroll
    for (int i = 0; i < 8; i++) row[t + i * 256] = v[i] * inv;
}

// ---------------- plain copy ----------------
__global__ void copy_k(const float* __restrict__ src, float* __restrict__ dst, int n)
{
    int i = blockIdx.x * blockDim.x + threadIdx.x;
    if (i < n) dst[i] = src[i];
}

// ---------------- host launcher ----------------
extern "C" void kernel_launch(void* const* d_in, const int* in_sizes, int n_in,
                              void* d_out, int out_size)
{
    const float* h    = (const float*)d_in[0];
    const float* Wdkv = (const float*)d_in[1];
    const float* bdkv = (const float*)d_in[2];
    const float* Wdq  = (const float*)d_in[3];
    const float* bdq  = (const float*)d_in[4];
    const float* Wuk  = (const float*)d_in[5];
    const float* buk  = (const float*)d_in[6];
    const float* Wuv  = (const float*)d_in[7];
    const float* buv  = (const float*)d_in[8];
    const float* Wuq  = (const float*)d_in[9];
    const float* buq  = (const float*)d_in[10];
    const float* Wqr  = (const float*)d_in[11];
    const float* bqr  = (const float*)d_in[12];
    const float* Wkr  = (const float*)d_in[13];
    const float* bkr  = (const float*)d_in[14];
    const float* outw = (const float*)d_in[15];
    const float* outb = (const float*)d_in[16];
    float* out = (float*)d_out;

    float *ckv, *cq, *qrot, *krot, *qb, *kb, *vb, *ao, *sc;
    cudaGetSymbolAddress((void**)&ckv,  g_ckv);
    cudaGetSymbolAddress((void**)&cq,   g_cq);
    cudaGetSymbolAddress((void**)&qrot, g_qrot);
    cudaGetSymbolAddress((void**)&krot, g_krot);
    cudaGetSymbolAddress((void**)&qb,   g_q);
    cudaGetSymbolAddress((void**)&kb,   g_k);
    cudaGetSymbolAddress((void**)&vb,   g_v);
    cudaGetSymbolAddress((void**)&ao,   g_ao);
    cudaGetSymbolAddress((void**)&sc,   g_sc);

    dim3 blk(256);
    auto grd = [](int M, int N, int Z) {
        return dim3((unsigned)((N + BN - 1) / BN), (unsigned)((M + BM - 1) / BM), (unsigned)Z);
    };

    // 1) down projections: c_kv, c_q  [4096,5120]@[5120,128]
    sgemm_k<false><<<grd(MROWS, DKV, 1), blk>>>(h, Wdkv, ckv, bdkv,
        MROWS, DKV, DM, DM, DKV, DKV, 1.0f, 0,0,0,0,0,0,0, 8);
    sgemm_k<false><<<grd(MROWS, DKV, 1), blk>>>(h, Wdq, cq, bdq,
        MROWS, DKV, DM, DM, DKV, DKV, 1.0f, 0,0,0,0,0,0,0, 8);

    // 2) up projections (per-head for base parts; z = head)
    sgemm_k<false><<<grd(MROWS, SPLITD, NH), blk>>>(ckv, Wuk, kb, buk,
        MROWS, SPLITD, DKV, DKV, NH*SPLITD, DM, 1.0f,
        0, 0, 0, SPLITD, 0, DH, SPLITD, 8);
    sgemm_k<false><<<grd(MROWS, SPLITD, NH), blk>>>(cq, Wuq, qb, buq,
        MROWS, SPLITD, DKV, DKV, NH*SPLITD, DM, 1.0f,
        0, 0, 0, SPLITD, 0, DH, SPLITD, 8);
    // v: full-width (naturally [B,S,H*640])
    sgemm_k<false><<<grd(MROWS, DM, 1), blk>>>(ckv, Wuv, vb, buv,
        MROWS, DM, DKV, DKV, DM, DM, 1.0f, 0,0,0,0,0,0,0, 8);
    // rotary parts (linear temp buffers)
    sgemm_k<false><<<grd(MROWS, DKV, 1), blk>>>(ckv, Wkr, krot, bkr,
        MROWS, DKV, DKV, DKV, DKV, DKV, 1.0f, 0,0,0,0,0,0,0, 8);
    sgemm_k<false><<<grd(MROWS, DKV, 1), blk>>>(cq, Wqr, qrot, bqr,
        MROWS, DKV, DKV, DKV, DKV, DKV, 1.0f, 0,0,0,0,0,0,0, 8);

    // 3) RoPE (writes into tail cols of q/k buffers; k variant also emits k_rot output)
    const size_t out_ckv_off  = (size_t)MROWS * DM;       // 20971520
    const size_t out_krot_off = out_ckv_off + (size_t)MROWS * DKV;
    bool full_out = (size_t)out_size >= out_krot_off + (size_t)MROWS * DKV;

    rope_k<<<(MROWS * DKV + 255) / 256, 256>>>(qrot, qb, nullptr);
    rope_k<<<(MROWS * DKV + 255) / 256, 256>>>(krot, kb,
        full_out ? (out + out_krot_off) : nullptr);

    if (full_out)
        copy_k<<<(MROWS * DKV + 255) / 256, 256>>>(ckv, out + out_ckv_off, MROWS * DKV);

    // 4) attention scores (NT): z = b*8+h, 16 batched GEMMs in one launch
    const long long SDM = (long long)SEQ * DM;
    const long long SS  = (long long)SEQ * SEQ;
    float inv_sqrt = 1.0f / sqrtf((float)DH);
    sgemm_k<true><<<grd(SEQ, SEQ, BATCH*NH), blk>>>(qb, kb, sc, nullptr,
        SEQ, SEQ, DH, DM, DM, SEQ, inv_sqrt,
        SDM, DH, SDM, DH, (long long)NH * SS, SS, 0, NH);

    // 5) softmax over 32768 rows
    softmax_k<<<BATCH * NH * SEQ, 256>>>(sc);

    // 6) attn @ v  -> g_ao ([B,S,H*640])
    sgemm_k<false><<<grd(SEQ, DH, BATCH*NH), blk>>>(sc, vb, ao, nullptr,
        SEQ, DH, SEQ, SEQ, DM, DM, 1.0f,
        (long long)NH * SS, SS, SDM, DH, SDM, DH, 0, NH);

    // 7) output projection -> d_out
    sgemm_k<false><<<grd(MROWS, DM, 1), blk>>>(ao, outw, out, outb,
        MROWS, DM, DM, DM, DM, DM, 1.0f, 0,0,0,0,0,0,0, 8);
}

// round 3
// speedup vs baseline: 4.3117x; 4.3117x over previous
#include <cuda_runtime.h>
#include <math.h>
#include <stdint.h>

// ---------------- problem constants ----------------
#define BATCH 2
#define SEQ   2048
#define DM    5120
#define NH    8
#define DH    640
#define DR    16
#define SPLITD 624
#define DKV   128
#define MROWS (BATCH*SEQ)        // 4096
#define NCOMP (NH*SPLITD)        // 4992 = 39*128

// ---------------- scratch (device globals; no allocs allowed) ----------------
__device__ __align__(16) float g_ckv [MROWS*DKV];
__device__ __align__(16) float g_cq  [MROWS*DKV];
__device__ __align__(16) float g_qrot[MROWS*DKV];
__device__ __align__(16) float g_krot[MROWS*DKV];
__device__ __align__(16) float g_kbt [(size_t)MROWS*NCOMP];
__device__ __align__(16) float g_qbt [(size_t)MROWS*NCOMP];
__device__ __align__(16) float g_q   [(size_t)MROWS*DM];
__device__ __align__(16) float g_k   [(size_t)MROWS*DM];
__device__ __align__(16) float g_v   [(size_t)MROWS*DM];
__device__ __align__(16) float g_vt  [(size_t)MROWS*DM];
__device__ __align__(16) float g_ao  [(size_t)MROWS*DM];
__device__ __align__(16) float g_sc  [(size_t)BATCH*NH*SEQ*SEQ];   // 256 MB scores
// transposed weights (B operands must be [N,K] K-major)
__device__ __align__(16) float g_wt_dkv[DKV*DM];
__device__ __align__(16) float g_wt_dq [DKV*DM];
__device__ __align__(16) float g_wt_uk [NCOMP*DKV];
__device__ __align__(16) float g_wt_uq [NCOMP*DKV];
__device__ __align__(16) float g_wt_uv [DM*DKV];
__device__ __align__(16) float g_wt_kr [DKV*DKV];
__device__ __align__(16) float g_wt_qr [DKV*DKV];
__device__ __align__(16) float g_wt_out[(size_t)DM*DM];

// ---------------- small PTX helpers ----------------
__device__ __forceinline__ uint32_t smem_u32(const void* p) {
    uint32_t a;
    asm("{ .reg .u64 t; cvta.to.shared.u64 t, %1; cvt.u32.u64 %0, t; }" : "=r"(a) : "l"(p));
    return a;
}
__device__ __forceinline__ void cp16(uint32_t dst, const void* src) {
    asm volatile("cp.async.cg.shared.global [%0], [%1], 16;" :: "r"(dst), "l"(src) : "memory");
}
#define CP_COMMIT() asm volatile("cp.async.commit_group;" ::: "memory")
#define CP_WAIT(n)  asm volatile("cp.async.wait_group %0;" :: "n"(n) : "memory")

__device__ __forceinline__ uint32_t f2t(float x) {
    uint32_t r;
    asm("cvt.rna.tf32.f32 %0, %1;" : "=r"(r) : "f"(x));
    return r;
}
__device__ __forceinline__ void mma_tf32(float* c, const uint32_t* a, uint32_t b0, uint32_t b1) {
    asm volatile("mma.sync.aligned.m16n8k8.row.col.f32.tf32.tf32.f32 "
                 "{%0,%1,%2,%3}, {%4,%5,%6,%7}, {%8,%9}, {%0,%1,%2,%3};"
                 : "+f"(c[0]), "+f"(c[1]), "+f"(c[2]), "+f"(c[3])
                 : "r"(a[0]), "r"(a[1]), "r"(a[2]), "r"(a[3]), "r"(b0), "r"(b1));
}

// ============================================================================
// tf32 mma.sync GEMM: C[M,N] = alpha * A[M,K] * B[N,K]^T (+ bias)
// M%128==0, N%128==0, K%16==0, 256 threads, double-buffered cp.async pipeline
// ============================================================================
#define BKQ 16
#define SPAD 20    // BK + 4 pad, conflict-free for fragment loads

__global__ __launch_bounds__(256)
void mmagemm(const float* __restrict__ A, const float* __restrict__ B,
             float* __restrict__ C, const float* __restrict__ bias,
             int M, int N, int K, int lda, int ldb, int ldc, float alpha,
             long long sAhi, long long sAlo, long long sBhi, long long sBlo,
             long long sChi, long long sClo, int zdiv)
{
    __shared__ float As[2][128][SPAD];
    __shared__ float Bs[2][128][SPAD];

    int tid  = threadIdx.x;
    int warp = tid >> 5;
    int lane = tid & 31;
    int wr = warp >> 1;          // 0..3 warp row
    int wc = warp & 1;           // 0..1 warp col
    int qid = lane >> 2;         // 0..7
    int tig = lane & 3;          // 0..3

    int z  = blockIdx.z;
    int zh = z / zdiv, zl = z % zdiv;
    A += zh * sAhi + zl * sAlo;
    B += zh * sBhi + zl * sBlo;
    C += zh * sChi + zl * sClo;

    int row0 = blockIdx.y * 128, col0 = blockIdx.x * 128;
    const float* Ab = A + (size_t)row0 * lda;
    const float* Bb = B + (size_t)col0 * ldb;

    // per-thread load coords: 512 float4 chunks per tile per operand
    int lr0 = tid >> 2,           lc0 = (tid & 3) * 4;
    int lr1 = (tid + 256) >> 2,   lc1 = lc0;
    uint32_t sA0[2], sA1[2], sB0[2], sB1[2];
#pragma unroll
    for (int s = 0; s < 2; s++) {
        sA0[s] = smem_u32(&As[s][lr0][lc0]);
        sA1[s] = smem_u32(&As[s][lr1][lc1]);
        sB0[s] = smem_u32(&Bs[s][lr0][lc0]);
        sB1[s] = smem_u32(&Bs[s][lr1][lc1]);
    }

    float acc[2][8][4];
#pragma unroll
    for (int mi = 0; mi < 2; mi++)
#pragma unroll
        for (int ni = 0; ni < 8; ni++)
#pragma unroll
            for (int i = 0; i < 4; i++) acc[mi][ni][i] = 0.0f;

    int T = K / BKQ;

    // prologue: tile 0
    {
        cp16(sA0[0], Ab + (size_t)lr0 * lda + lc0);
        cp16(sA1[0], Ab + (size_t)lr1 * lda + lc1);
        cp16(sB0[0], Bb + (size_t)lr0 * ldb + lc0);
        cp16(sB1[0], Bb + (size_t)lr1 * ldb + lc1);
        CP_COMMIT();
    }

    for (int t = 0; t < T; t++) {
        if (t + 1 < T) {
            int s = (t + 1) & 1;
            int k0 = (t + 1) * BKQ;
            cp16(sA0[s], Ab + (size_t)lr0 * lda + k0 + lc0);
            cp16(sA1[s], Ab + (size_t)lr1 * lda + k0 + lc1);
            cp16(sB0[s], Bb + (size_t)lr0 * ldb + k0 + lc0);
            cp16(sB1[s], Bb + (size_t)lr1 * ldb + k0 + lc1);
            CP_COMMIT();
            CP_WAIT(1);
        } else {
            CP_WAIT(0);
        }
        __syncthreads();

        int s = t & 1;
#pragma unroll
        for (int ks = 0; ks < 2; ks++) {
            int k0 = ks * 8;
            uint32_t a[2][4];
#pragma unroll
            for (int mi = 0; mi < 2; mi++) {
                int rb = wr * 32 + mi * 16;
                a[mi][0] = f2t(As[s][rb + qid    ][k0 + tig    ]);
                a[mi][1] = f2t(As[s][rb + qid + 8][k0 + tig    ]);
                a[mi][2] = f2t(As[s][rb + qid    ][k0 + tig + 4]);
                a[mi][3] = f2t(As[s][rb + qid + 8][k0 + tig + 4]);
            }
#pragma unroll
            for (int ni = 0; ni < 8; ni++) {
                int cb = wc * 64 + ni * 8;
                uint32_t b0 = f2t(Bs[s][cb + qid][k0 + tig    ]);
                uint32_t b1 = f2t(Bs[s][cb + qid][k0 + tig + 4]);
                mma_tf32(acc[0][ni], a[0], b0, b1);
                mma_tf32(acc[1][ni], a[1], b0, b1);
            }
        }
        __syncthreads();
    }

    // epilogue
#pragma unroll
    for (int mi = 0; mi < 2; mi++) {
        int rg = row0 + wr * 32 + mi * 16 + qid;
#pragma unroll
        for (int ni = 0; ni < 8; ni++) {
            int cg = col0 + wc * 64 + ni * 8 + tig * 2;
            float bx = 0.0f, by = 0.0f;
            if (bias) { bx = bias[cg]; by = bias[cg + 1]; }
            float2 v0 = make_float2(alpha * acc[mi][ni][0] + bx, alpha * acc[mi][ni][1] + by);
            float2 v1 = make_float2(alpha * acc[mi][ni][2] + bx, alpha * acc[mi][ni][3] + by);
            *reinterpret_cast<float2*>(C + (size_t)rg * ldc + cg) = v0;
            *reinterpret_cast<float2*>(C + (size_t)(rg + 8) * ldc + cg) = v1;
        }
    }
}

// ============================================================================
// transpose: out[c][r] = in[r][c], dims multiples of 32, batched
// ============================================================================
__global__ __launch_bounds__(256)
void transpose_k(const float* __restrict__ in, float* __restrict__ out,
                 int ldi, int ldo,
                 long long siHi, long long siLo, long long soHi, long long soLo, int zdiv)
{
    int z = blockIdx.z;
    in  += (z / zdiv) * siHi + (z % zdiv) * siLo;
    out += (z / zdiv) * soHi + (z % zdiv) * soLo;
    __shared__ float t[32][33];
    int bx = blockIdx.x * 32, by = blockIdx.y * 32;
    int tx = threadIdx.x & 31, ty = threadIdx.x >> 5;
#pragma unroll
    for (int i = 0; i < 4; i++)
        t[ty + 8 * i][tx] = in[(size_t)(by + ty + 8 * i) * ldi + bx + tx];
    __syncthreads();
#pragma unroll
    for (int i = 0; i < 4; i++)
        out[(size_t)(bx + ty + 8 * i) * ldo + by + tx] = t[tx][ty + 8 * i];
}

// pack compact [4096,4992] -> [4096,5120] head layout (cols h*640+0..623)
__global__ void pack_k(const float* __restrict__ src, float* __restrict__ dst)
{
    int idx = blockIdx.x * blockDim.x + threadIdx.x;   // float4 index
    if (idx >= MROWS * (NCOMP / 4)) return;
    int m = idx / (NCOMP / 4);
    int q = idx % (NCOMP / 4);
    int h = q / (SPLITD / 4);
    int j = q % (SPLITD / 4);
    const float4 v = *reinterpret_cast<const float4*>(src + (size_t)m * NCOMP + q * 4);
    *reinterpret_cast<float4*>(dst + (size_t)m * DM + h * DH + j * 4) = v;
}

// ---------------- RoPE ----------------
__global__ void rope_k(const float* __restrict__ rot, float* __restrict__ dst,
                       float* __restrict__ rout)
{
    int idx = blockIdx.x * blockDim.x + threadIdx.x;
    if (idx >= MROWS * DKV) return;
    int m = idx >> 7;
    int c = idx & 127;
    int h = c >> 4;
    int d = c & 15;
    int j = d & 7;
    int s = m & (SEQ - 1);
    float t = (float)s * (1.0f / 40.0f);
    float invf = __expf(-(float)j * 0.86346941f);  // ln(1000)/8
    float ang = t * invf;
    float sn, cs;
    sincosf(ang, &sn, &cs);
    float x = rot[idx];
    float p = rot[(m << 7) + (h << 4) + ((d < 8) ? d + 8 : d - 8)];
    float val = x * cs + ((d < 8) ? -p : p) * sn;
    dst[(size_t)m * DM + h * DH + SPLITD + d] = val;
    if (rout) rout[idx] = val;
}

// ---------------- softmax over rows of length SEQ ----------------
__global__ __launch_bounds__(256) void softmax_k(float* __restrict__ s)
{
    float* row = s + (size_t)blockIdx.x * SEQ;
    int t = threadIdx.x;
    float v[8];
    float mx = -1e30f;
#pragma unroll
    for (int i = 0; i < 8; i++) { v[i] = row[t + i * 256]; mx = fmaxf(mx, v[i]); }
    __shared__ float red[256];
    red[t] = mx; __syncthreads();
    for (int off = 128; off > 0; off >>= 1) {
        if (t < off) red[t] = fmaxf(red[t], red[t + off]);
        __syncthreads();
    }
    mx = red[0]; __syncthreads();
    float sum = 0.0f;
#pragma unroll
    for (int i = 0; i < 8; i++) { v[i] = __expf(v[i] - mx); sum += v[i]; }
    red[t] = sum; __syncthreads();
    for (int off = 128; off > 0; off >>= 1) {
        if (t < off) red[t] += red[t + off];
        __syncthreads();
    }
    float inv = 1.0f / red[0];
#pragma unroll
    for (int i = 0; i < 8; i++) row[t + i * 256] = v[i] * inv;
}

__global__ void copy_k(const float* __restrict__ src, float* __restrict__ dst, int n)
{
    int i = blockIdx.x * blockDim.x + threadIdx.x;
    if (i < n) dst[i] = src[i];
}

// ============================================================================
// host launcher
// ============================================================================
extern "C" void kernel_launch(void* const* d_in, const int* in_sizes, int n_in,
                              void* d_out, int out_size)
{
    const float* h    = (const float*)d_in[0];
    const float* Wdkv = (const float*)d_in[1];
    const float* bdkv = (const float*)d_in[2];
    const float* Wdq  = (const float*)d_in[3];
    const float* bdq  = (const float*)d_in[4];
    const float* Wuk  = (const float*)d_in[5];
    const float* buk  = (const float*)d_in[6];
    const float* Wuv  = (const float*)d_in[7];
    const float* buv  = (const float*)d_in[8];
    const float* Wuq  = (const float*)d_in[9];
    const float* buq  = (const float*)d_in[10];
    const float* Wqr  = (const float*)d_in[11];
    const float* bqr  = (const float*)d_in[12];
    const float* Wkr  = (const float*)d_in[13];
    const float* bkr  = (const float*)d_in[14];
    const float* outw = (const float*)d_in[15];
    const float* outb = (const float*)d_in[16];
    float* out = (float*)d_out;

    float *ckv, *cq, *qrot, *krot, *kbt, *qbt, *qb, *kb, *vb, *vt, *ao, *sc;
    float *wt_dkv, *wt_dq, *wt_uk, *wt_uq, *wt_uv, *wt_kr, *wt_qr, *wt_out;
    cudaGetSymbolAddress((void**)&ckv,  g_ckv);
    cudaGetSymbolAddress((void**)&cq,   g_cq);
    cudaGetSymbolAddress((void**)&qrot, g_qrot);
    cudaGetSymbolAddress((void**)&krot, g_krot);
    cudaGetSymbolAddress((void**)&kbt,  g_kbt);
    cudaGetSymbolAddress((void**)&qbt,  g_qbt);
    cudaGetSymbolAddress((void**)&qb,   g_q);
    cudaGetSymbolAddress((void**)&kb,   g_k);
    cudaGetSymbolAddress((void**)&vb,   g_v);
    cudaGetSymbolAddress((void**)&vt,   g_vt);
    cudaGetSymbolAddress((void**)&ao,   g_ao);
    cudaGetSymbolAddress((void**)&sc,   g_sc);
    cudaGetSymbolAddress((void**)&wt_dkv, g_wt_dkv);
    cudaGetSymbolAddress((void**)&wt_dq,  g_wt_dq);
    cudaGetSymbolAddress((void**)&wt_uk,  g_wt_uk);
    cudaGetSymbolAddress((void**)&wt_uq,  g_wt_uq);
    cudaGetSymbolAddress((void**)&wt_uv,  g_wt_uv);
    cudaGetSymbolAddress((void**)&wt_kr,  g_wt_kr);
    cudaGetSymbolAddress((void**)&wt_qr,  g_wt_qr);
    cudaGetSymbolAddress((void**)&wt_out, g_wt_out);

    dim3 b256(256);
    // ---- weight transposes (B operands become [N,K] K-major) ----
    transpose_k<<<dim3(DKV/32, DM/32, 1), b256>>>(Wdkv, wt_dkv, DKV, DM, 0,0,0,0, 1);
    transpose_k<<<dim3(DKV/32, DM/32, 1), b256>>>(Wdq,  wt_dq,  DKV, DM, 0,0,0,0, 1);
    transpose_k<<<dim3(NCOMP/32, DKV/32, 1), b256>>>(Wuk, wt_uk, NCOMP, DKV, 0,0,0,0, 1);
    transpose_k<<<dim3(NCOMP/32, DKV/32, 1), b256>>>(Wuq, wt_uq, NCOMP, DKV, 0,0,0,0, 1);
    transpose_k<<<dim3(DM/32, DKV/32, 1), b256>>>(Wuv, wt_uv, DM, DKV, 0,0,0,0, 1);
    transpose_k<<<dim3(DKV/32, DKV/32, 1), b256>>>(Wkr, wt_kr, DKV, DKV, 0,0,0,0, 1);
    transpose_k<<<dim3(DKV/32, DKV/32, 1), b256>>>(Wqr, wt_qr, DKV, DKV, 0,0,0,0, 1);
    transpose_k<<<dim3(DM/32, DM/32, 1), b256>>>(outw, wt_out, DM, DM, 0,0,0,0, 1);

    dim3 blk(256);
    auto grd = [](int M, int N, int Z) { return dim3((unsigned)(N / 128), (unsigned)(M / 128), (unsigned)Z); };

    // 1) down projections
    mmagemm<<<grd(MROWS, DKV, 1), blk>>>(h, wt_dkv, ckv, bdkv,
        MROWS, DKV, DM, DM, DM, DKV, 1.0f, 0,0,0,0,0,0, 1);
    mmagemm<<<grd(MROWS, DKV, 1), blk>>>(h, wt_dq, cq, bdq,
        MROWS, DKV, DM, DM, DM, DKV, 1.0f, 0,0,0,0,0,0, 1);

    // 2) up projections (compact base buffers) + v + rotary
    mmagemm<<<grd(MROWS, NCOMP, 1), blk>>>(ckv, wt_uk, kbt, buk,
        MROWS, NCOMP, DKV, DKV, DKV, NCOMP, 1.0f, 0,0,0,0,0,0, 1);
    mmagemm<<<grd(MROWS, NCOMP, 1), blk>>>(cq, wt_uq, qbt, buq,
        MROWS, NCOMP, DKV, DKV, DKV, NCOMP, 1.0f, 0,0,0,0,0,0, 1);
    mmagemm<<<grd(MROWS, DM, 1), blk>>>(ckv, wt_uv, vb, buv,
        MROWS, DM, DKV, DKV, DKV, DM, 1.0f, 0,0,0,0,0,0, 1);
    mmagemm<<<grd(MROWS, DKV, 1), blk>>>(ckv, wt_kr, krot, bkr,
        MROWS, DKV, DKV, DKV, DKV, DKV, 1.0f, 0,0,0,0,0,0, 1);
    mmagemm<<<grd(MROWS, DKV, 1), blk>>>(cq, wt_qr, qrot, bqr,
        MROWS, DKV, DKV, DKV, DKV, DKV, 1.0f, 0,0,0,0,0,0, 1);

    // pack compact bases into [*,5120] head layout
    pack_k<<<(MROWS * (NCOMP/4) + 255) / 256, 256>>>(kbt, kb);
    pack_k<<<(MROWS * (NCOMP/4) + 255) / 256, 256>>>(qbt, qb);

    // 3) RoPE + secondary outputs
    const size_t out_ckv_off  = (size_t)MROWS * DM;
    const size_t out_krot_off = out_ckv_off + (size_t)MROWS * DKV;
    bool full_out = (size_t)out_size >= out_krot_off + (size_t)MROWS * DKV;

    rope_k<<<(MROWS * DKV + 255) / 256, 256>>>(qrot, qb, nullptr);
    rope_k<<<(MROWS * DKV + 255) / 256, 256>>>(krot, kb,
        full_out ? (out + out_krot_off) : nullptr);
    if (full_out)
        copy_k<<<(MROWS * DKV + 255) / 256, 256>>>(ckv, out + out_ckv_off, MROWS * DKV);

    // V transpose per (b,h): [2048,640] -> [640,2048]
    const long long SDM = (long long)SEQ * DM;
    const long long HDS = (long long)DH * SEQ;
    transpose_k<<<dim3(DH/32, SEQ/32, BATCH*NH), b256>>>(vb, vt, DM, SEQ,
        SDM, DH, (long long)NH * HDS, HDS, NH);

    // 4) attention scores: z = b*8+h
    const long long SS = (long long)SEQ * SEQ;
    float inv_sqrt = 1.0f / sqrtf((float)DH);
    mmagemm<<<grd(SEQ, SEQ, BATCH*NH), blk>>>(qb, kb, sc, nullptr,
        SEQ, SEQ, DH, DM, DM, SEQ, inv_sqrt,
        SDM, DH, SDM, DH, (long long)NH * SS, SS, NH);

    // 5) softmax
    softmax_k<<<BATCH * NH * SEQ, 256>>>(sc);

    // 6) attn @ v
    mmagemm<<<grd(SEQ, DH, BATCH*NH), blk>>>(sc, vt, ao, nullptr,
        SEQ, DH, SEQ, SEQ, SEQ, DM, 1.0f,
        (long long)NH * SS, SS, (long long)NH * HDS, HDS, SDM, DH, NH);

    // 7) output projection
    mmagemm<<<grd(MROWS, DM, 1), blk>>>(ao, wt_out, out, outb,
        MROWS, DM, DM, DM, DM, DM, 1.0f, 0,0,0,0,0,0, 1);
}